// round 3
// baseline (speedup 1.0000x reference)
#include <cuda_runtime.h>

// IntDVF: scaling-and-squaring integration of a stationary velocity field.
//   ddf = dvf / 2^7;  repeat 7x: ddf = ddf + warp(ddf, ddf)
// Shapes: (B=2, 128,128,128, 3) float32, trilinear sampling with clamped indices.
//
// Strategy: pad channels to float4 so every trilinear corner is one LDG.128.
// Two __device__ ping-pong buffers; scale fused into pad pass; final step
// writes un-padded float3 directly into d_out.

#define DDIM 128
#define DN   (DDIM * DDIM * DDIM)   // 2097152 voxels per batch
#define NBATCH 2
#define NVOX (NBATCH * DN)          // 4194304
#define NTHREADS 256
#define NBLOCKS (NVOX / NTHREADS)   // 16384

__device__ float4 g_bufA[NVOX];
__device__ float4 g_bufB[NVOX];

// dvf (AoS float3) -> padded float4, scaled by 1/2^NUM_STEPS
__global__ __launch_bounds__(NTHREADS) void k_scale_pad(const float* __restrict__ in) {
    const float S = 1.0f / 128.0f;  // 2^-7
    int t = blockIdx.x * NTHREADS + threadIdx.x;       // t < NVOX always
    const float* p = in + (size_t)t * 3;
    g_bufA[t] = make_float4(p[0] * S, p[1] * S, p[2] * S, 0.0f);
}

// One integration step: dst = src + trilinear_sample(src, grid + src).
// SRC_IS_A selects ping-pong direction; PACK writes float3 to gmem out.
template <bool SRC_IS_A, bool PACK>
__global__ __launch_bounds__(NTHREADS) void k_step(float* __restrict__ out3) {
    const float4* __restrict__ srcg = SRC_IS_A ? g_bufA : g_bufB;
    float4* __restrict__ dstg       = SRC_IS_A ? g_bufB : g_bufA;

    int t = blockIdx.x * NTHREADS + threadIdx.x;       // t < NVOX always
    int b = t >> 21;                                   // DN = 2^21
    int v = t & (DN - 1);
    int z = v & 127;
    int y = (v >> 7) & 127;
    int x = v >> 14;

    const float4* __restrict__ base = srcg + (size_t)b * DN;

    float4 d = base[v];

    float lx = (float)x + d.x;
    float ly = (float)y + d.y;
    float lz = (float)z + d.z;

    float fx = floorf(lx), fy = floorf(ly), fz = floorf(lz);
    float wx1 = lx - fx, wy1 = ly - fy, wz1 = lz - fz;
    float wx0 = 1.0f - wx1, wy0 = 1.0f - wy1, wz0 = 1.0f - wz1;

    int jx = (int)fx, jy = (int)fy, jz = (int)fz;
    int ix0 = min(max(jx, 0), 127);
    int ix1 = min(max(jx + 1, 0), 127);
    int iy0 = min(max(jy, 0), 127);
    int iy1 = min(max(jy + 1, 0), 127);
    int iz0 = min(max(jz, 0), 127);
    int iz1 = min(max(jz + 1, 0), 127);

    int X0 = ix0 << 14, X1 = ix1 << 14;
    int Y0 = iy0 << 7,  Y1 = iy1 << 7;

    // 8 corner fetches (each one LDG.128) — issue all before consuming for MLP.
    float4 c000 = base[X0 + Y0 + iz0];
    float4 c001 = base[X0 + Y0 + iz1];
    float4 c010 = base[X0 + Y1 + iz0];
    float4 c011 = base[X0 + Y1 + iz1];
    float4 c100 = base[X1 + Y0 + iz0];
    float4 c101 = base[X1 + Y0 + iz1];
    float4 c110 = base[X1 + Y1 + iz0];
    float4 c111 = base[X1 + Y1 + iz1];

    float w00 = wx0 * wy0;
    float w01 = wx0 * wy1;
    float w10 = wx1 * wy0;
    float w11 = wx1 * wy1;

    float w000 = w00 * wz0, w001 = w00 * wz1;
    float w010 = w01 * wz0, w011 = w01 * wz1;
    float w100 = w10 * wz0, w101 = w10 * wz1;
    float w110 = w11 * wz0, w111 = w11 * wz1;

    float ax = d.x, ay = d.y, az = d.z;
    ax = fmaf(w000, c000.x, ax); ay = fmaf(w000, c000.y, ay); az = fmaf(w000, c000.z, az);
    ax = fmaf(w001, c001.x, ax); ay = fmaf(w001, c001.y, ay); az = fmaf(w001, c001.z, az);
    ax = fmaf(w010, c010.x, ax); ay = fmaf(w010, c010.y, ay); az = fmaf(w010, c010.z, az);
    ax = fmaf(w011, c011.x, ax); ay = fmaf(w011, c011.y, ay); az = fmaf(w011, c011.z, az);
    ax = fmaf(w100, c100.x, ax); ay = fmaf(w100, c100.y, ay); az = fmaf(w100, c100.z, az);
    ax = fmaf(w101, c101.x, ax); ay = fmaf(w101, c101.y, ay); az = fmaf(w101, c101.z, az);
    ax = fmaf(w110, c110.x, ax); ay = fmaf(w110, c110.y, ay); az = fmaf(w110, c110.z, az);
    ax = fmaf(w111, c111.x, ax); ay = fmaf(w111, c111.y, ay); az = fmaf(w111, c111.z, az);

    if (PACK) {
        float* q = out3 + (size_t)t * 3;
        q[0] = ax; q[1] = ay; q[2] = az;
    } else {
        dstg[t] = make_float4(ax, ay, az, 0.0f);
    }
}

extern "C" void kernel_launch(void* const* d_in, const int* in_sizes, int n_in,
                              void* d_out, int out_size) {
    const float* dvf = (const float*)d_in[0];
    float* out = (float*)d_out;

    // ddf0 = dvf / 128, padded into A
    k_scale_pad<<<NBLOCKS, NTHREADS>>>(dvf);

    // 7 squaring steps, ping-pong A<->B; final step un-pads into d_out.
    k_step<true,  false><<<NBLOCKS, NTHREADS>>>(nullptr);  // A -> B   (step 1)
    k_step<false, false><<<NBLOCKS, NTHREADS>>>(nullptr);  // B -> A   (step 2)
    k_step<true,  false><<<NBLOCKS, NTHREADS>>>(nullptr);  // A -> B   (step 3)
    k_step<false, false><<<NBLOCKS, NTHREADS>>>(nullptr);  // B -> A   (step 4)
    k_step<true,  false><<<NBLOCKS, NTHREADS>>>(nullptr);  // A -> B   (step 5)
    k_step<false, false><<<NBLOCKS, NTHREADS>>>(nullptr);  // B -> A   (step 6)
    k_step<true,  true ><<<NBLOCKS, NTHREADS>>>(out);      // A -> out (step 7)
}